// round 16
// baseline (speedup 1.0000x reference)
#include <cuda_runtime.h>
#include <cuda_fp16.h>
#include <stdint.h>

#define SEQ 4096
#define DIM 1024
#define NH  16
#define HD  64

// ---------------- fp16 scratch (device globals; no allocation allowed) -----
__device__ __align__(128) __half g_xh [SEQ * DIM];
__device__ __align__(128) __half g_wqh[DIM * DIM];
__device__ __align__(128) __half g_wkh[DIM * DIM];
__device__ __align__(128) __half g_wvh[DIM * DIM];
__device__ __align__(128) __half g_woh[DIM * DIM];
__device__ __align__(128) __half g_qh [NH * SEQ * HD];   // [h][s][hd]
__device__ __align__(128) __half g_kh [NH * SEQ * HD];   // [h][s][hd]
__device__ __align__(128) __half g_vh [NH * SEQ * HD];   // [h][s][hd]
__device__ __align__(128) __half g_ctxh[SEQ * DIM];      // [s][d]

// ========================= PTX helpers =====================================
__device__ __forceinline__ uint32_t smem_u32(const void* p) {
    uint32_t a;
    asm("{ .reg .u64 t; cvta.to.shared.u64 t, %1; cvt.u32.u64 %0, t; }"
        : "=r"(a) : "l"(p));
    return a;
}
__device__ __forceinline__ void ldsm4(uint32_t* r, uint32_t a) {
    asm volatile("ldmatrix.sync.aligned.m8n8.x4.shared.b16 {%0,%1,%2,%3}, [%4];"
                 : "=r"(r[0]), "=r"(r[1]), "=r"(r[2]), "=r"(r[3]) : "r"(a));
}
__device__ __forceinline__ void ldsm4t(uint32_t* r, uint32_t a) {
    asm volatile("ldmatrix.sync.aligned.m8n8.x4.trans.shared.b16 {%0,%1,%2,%3}, [%4];"
                 : "=r"(r[0]), "=r"(r[1]), "=r"(r[2]), "=r"(r[3]) : "r"(a));
}
__device__ __forceinline__ void mma16816(float* d, const uint32_t* a,
                                         uint32_t b0, uint32_t b1) {
    asm volatile(
        "mma.sync.aligned.m16n8k16.row.col.f32.f16.f16.f32 "
        "{%0,%1,%2,%3}, {%4,%5,%6,%7}, {%8,%9}, {%0,%1,%2,%3};"
        : "+f"(d[0]), "+f"(d[1]), "+f"(d[2]), "+f"(d[3])
        : "r"(a[0]), "r"(a[1]), "r"(a[2]), "r"(a[3]), "r"(b0), "r"(b1));
}
__device__ __forceinline__ float ex2f(float x) {
    float y;
    asm("ex2.approx.f32 %0, %1;" : "=f"(y) : "f"(x));
    return y;
}
// packed fp16x2 exp2: one MUFU op for two probabilities
__device__ __forceinline__ uint32_t ex2_h2(uint32_t a) {
    uint32_t y;
    asm("ex2.approx.f16x2 %0, %1;" : "=r"(y) : "r"(a));
    return y;
}
#define CP16(sa, gp) \
    asm volatile("cp.async.cg.shared.global [%0], [%1], 16;" :: "r"(sa), "l"(gp))
#define CP_COMMIT()  asm volatile("cp.async.commit_group;" ::: "memory")
#define CP_WAIT_G1() asm volatile("cp.async.wait_group 1;" ::: "memory")
#define CP_WAIT_G0() asm volatile("cp.async.wait_group 0;" ::: "memory")

__device__ __forceinline__ uint32_t pack_h2(float a, float b) {
    __half2 h = __floats2half2_rn(a, b);
    return *(uint32_t*)&h;
}

// =========================== fp32 -> fp16 convert ==========================
__global__ __launch_bounds__(256) void convert_kernel(
    const float* __restrict__ x,  const float* __restrict__ wq,
    const float* __restrict__ wk, const float* __restrict__ wv,
    const float* __restrict__ wo)
{
    const int i = blockIdx.x * 256 + threadIdx.x;   // float4 index
    const int XN = SEQ * DIM / 4, WN = DIM * DIM / 4;
    const float* src; __half* dst; int off;
    if (i < XN) { src = x; dst = g_xh; off = i; }
    else {
        int j = i - XN; int w = j / WN; off = j - w * WN;
        src = (w == 0) ? wq : (w == 1) ? wk : (w == 2) ? wv : wo;
        dst = (w == 0) ? g_wqh : (w == 1) ? g_wkh : (w == 2) ? g_wvh : g_woh;
    }
    float4 v = ((const float4*)src)[off];
    uint2 u;
    u.x = pack_h2(v.x, v.y);
    u.y = pack_h2(v.z, v.w);
    ((uint2*)dst)[off] = u;
}

// ================== HMMA GEMM: Y[m][n] = sum_k A[m][k] B[n][k] =============
// BM=BN=128, BK=64, 256 threads = 8 warps (4m x 2n), 32x64 per-warp tile.
// 3-stage cp.async pipeline, single __syncthreads per 64-wide K step.
#define BK 64
#define AP 72                        // smem pitch in halfs (144B rows)
#define G_ABYTES (128 * AP * 2)      // 18432 B per stage per operand
#define G_STAGE  (2 * G_ABYTES)      // 36864 B per stage (A + B)
#define G_NSTAGE 3
#define GEMM_SMEM_TOT (G_NSTAGE * G_STAGE)   // 110592 B
#define G_NC (DIM / BK)              // 16

__device__ __forceinline__ void hgemm_load(
    char* smem, const __half* __restrict__ Ag, const __half* __restrict__ Bg,
    int c, int tid)
{
    const uint32_t base = smem_u32(smem + (c % G_NSTAGE) * G_STAGE);
    // A and B: 128 rows x 8 chunks of 16B each = 1024 cp.async per operand
#pragma unroll
    for (int i = 0; i < 4; i++) {
        int idx = i * 256 + tid;
        int r = idx >> 3, q = idx & 7;
        CP16(base + r * (AP * 2) + q * 16, Ag + (size_t)r * DIM + c * BK + q * 8);
        CP16(base + G_ABYTES + r * (AP * 2) + q * 16,
             Bg + (size_t)r * DIM + c * BK + q * 8);
    }
}

__device__ __forceinline__ void hgemm_mainloop(
    char* smem, const __half* __restrict__ Ag, const __half* __restrict__ Bg,
    float acc[2][8][4])
{
    const int tid = threadIdx.x;
    const int l = tid & 31, wid = tid >> 5;
    const int wm = wid >> 1, wn = wid & 1;

#pragma unroll
    for (int mi = 0; mi < 2; mi++)
#pragma unroll
        for (int f = 0; f < 8; f++)
#pragma unroll
            for (int e = 0; e < 4; e++) acc[mi][f][e] = 0.f;

    // prologue: 2 stages in flight
#pragma unroll
    for (int s = 0; s < 2; s++) { hgemm_load(smem, Ag, Bg, s, tid); CP_COMMIT(); }

    // per-lane ldmatrix offsets (halfs)
    const int aRow = wm * 32 + (l & 15);
    const int aCol = (l >> 4) << 3;
    const int bRow = wn * 64 + (l & 7) + ((l >> 4) << 3);
    const int bCol = ((l >> 3) & 1) << 3;

    for (int c = 0; c < G_NC; c++) {
        CP_WAIT_G1();
        __syncthreads();
        if (c + 2 < G_NC) hgemm_load(smem, Ag, Bg, c + 2, tid);
        CP_COMMIT();   // unconditional: keeps wait_group accounting uniform

        const uint32_t aS = smem_u32(smem + (c % G_NSTAGE) * G_STAGE);
        const uint32_t bS = aS + G_ABYTES;
#pragma unroll
        for (int ks = 0; ks < 4; ks++) {
            const int k0 = ks * 16;
            uint32_t af[2][4];
#pragma unroll
            for (int mi = 0; mi < 2; mi++)
                ldsm4(af[mi], aS + ((aRow + mi * 16) * AP + k0 + aCol) * 2);
            uint32_t bf[4][4];
#pragma unroll
            for (int g = 0; g < 4; g++)
                ldsm4(bf[g], bS + ((bRow + g * 16) * AP + k0 + bCol) * 2);
#pragma unroll
            for (int mi = 0; mi < 2; mi++)
#pragma unroll
                for (int f = 0; f < 8; f++) {
                    const int g = f >> 1, o = (f & 1) * 2;
                    mma16816(acc[mi][f], af[mi], bf[g][o], bf[g][o + 1]);
                }
        }
    }
}

__global__ __launch_bounds__(256, 2) void gemm_proj_kernel()
{
    extern __shared__ char smem[];
    const int tid = threadIdx.x;
    const int l = tid & 31, wid = tid >> 5;
    const int wm = wid >> 1, wn = wid & 1;
    const int m0 = blockIdx.y * 128, n0 = blockIdx.x * 128;
    const int z = blockIdx.z;
    const __half* B = (z == 0) ? g_wqh : (z == 1) ? g_wkh : g_wvh;
    __half* dst = (z == 0) ? g_qh : (z == 1) ? g_kh : g_vh;

    float acc[2][8][4];
    hgemm_mainloop(smem, g_xh + (size_t)m0 * DIM, B + (size_t)n0 * DIM, acc);

#pragma unroll
    for (int mi = 0; mi < 2; mi++)
#pragma unroll
        for (int f = 0; f < 8; f++) {
            const int r  = m0 + wm * 32 + mi * 16 + (l >> 2);
            const int cc = n0 + wn * 64 + f * 8 + ((l & 3) << 1);
            const int h = cc >> 6, hd = cc & 63;
            const size_t base = ((size_t)h * SEQ + r) * HD + hd;
            *(__half2*)&dst[base] = __floats2half2_rn(acc[mi][f][0], acc[mi][f][1]);
            *(__half2*)&dst[base + 8 * HD] =
                __floats2half2_rn(acc[mi][f][2], acc[mi][f][3]);
        }
}

__global__ __launch_bounds__(256, 2) void out_proj_kernel(
    const float* __restrict__ bo, float* __restrict__ out)
{
    extern __shared__ char smem[];
    const int tid = threadIdx.x;
    const int l = tid & 31, wid = tid >> 5;
    const int wm = wid >> 1, wn = wid & 1;
    const int m0 = blockIdx.y * 128, n0 = blockIdx.x * 128;

    float acc[2][8][4];
    hgemm_mainloop(smem, g_ctxh + (size_t)m0 * DIM, g_woh + (size_t)n0 * DIM, acc);

#pragma unroll
    for (int mi = 0; mi < 2; mi++)
#pragma unroll
        for (int f = 0; f < 8; f++) {
            const int r  = m0 + wm * 32 + mi * 16 + (l >> 2);
            const int cc = n0 + wn * 64 + f * 8 + ((l & 3) << 1);
            const float2 b2 = *(const float2*)&bo[cc];
            float2 v0, v1;
            v0.x = acc[mi][f][0] + b2.x; v0.y = acc[mi][f][1] + b2.y;
            v1.x = acc[mi][f][2] + b2.x; v1.y = acc[mi][f][3] + b2.y;
            *(float2*)&out[(size_t)r * DIM + cc] = v0;
            *(float2*)&out[(size_t)(r + 8) * DIM + cc] = v1;
        }
}

// ================== HMMA flash attention (causal, fp16) ====================
// 256 threads = 8 warps; warp w owns q-rows [w*16, w*16+16). BN=64 per iter.
// 3-stage cp.async K/V ring (prefetch distance 2), one barrier per iteration.
// Softmax runs in the exp2 domain with packed fp16x2 ex2 (half the MUFU ops);
// the row sum is computed from the quantized P, so l matches the PV numerator.
#define QP 72                        // smem pitch (halfs): 144B rows
#define A_QBYTES (128 * QP * 2)      // 18432
#define A_KVBYTES (64 * QP * 2)      // 9216
#define A_NSTAGE 3
#define A_KOFF(s) (A_QBYTES + (s) * A_KVBYTES)
#define A_VOFF(s) (A_QBYTES + A_NSTAGE * A_KVBYTES + (s) * A_KVBYTES)
#define ATTN_SMEM_TOT (A_QBYTES + 2 * A_NSTAGE * A_KVBYTES)   // 73728

__device__ __forceinline__ void attn_load_kv(
    char* smem, const __half* __restrict__ Kg, const __half* __restrict__ Vg,
    int j, int tid)
{
    const int s = j % A_NSTAGE;
    const uint32_t kB = smem_u32(smem + A_KOFF(s));
    const uint32_t vB = smem_u32(smem + A_VOFF(s));
#pragma unroll
    for (int i = 0; i < 2; i++) {
        int idx = i * 256 + tid;      // 0..511 chunks of 16B
        int r = idx >> 3, q = idx & 7;
        CP16(kB + r * (QP * 2) + q * 16, Kg + ((size_t)j * 64 + r) * HD + q * 8);
        CP16(vB + r * (QP * 2) + q * 16, Vg + ((size_t)j * 64 + r) * HD + q * 8);
    }
}

__global__ __launch_bounds__(256, 2) void attn_kernel()
{
    extern __shared__ char smem[];
    const int tid = threadIdx.x;
    const int l = tid & 31, wid = tid >> 5;
    const int qb = (gridDim.x - 1) - blockIdx.x;   // big blocks first
    const int h = blockIdx.y;

    const __half* Qg = g_qh + ((size_t)h * SEQ + (size_t)qb * 128) * HD;
    const __half* Kg = g_kh + (size_t)h * SEQ * HD;
    const __half* Vg = g_vh + (size_t)h * SEQ * HD;

    // kick off K/V tiles 0 and 1 before staging Q (jmax >= 1 always)
    attn_load_kv(smem, Kg, Vg, 0, tid);
    CP_COMMIT();
    attn_load_kv(smem, Kg, Vg, 1, tid);
    CP_COMMIT();

    // stage Q tile [128][64] -> pitch-72 smem
    __half* sQ = (__half*)smem;
#pragma unroll
    for (int i = 0; i < 4; i++) {
        int idx = i * 256 + tid;          // 0..1023 chunks of 16B
        int r = idx >> 3, q = idx & 7;
        *(uint4*)(sQ + r * QP + q * 8) = *(const uint4*)(Qg + (size_t)r * HD + q * 8);
    }
    __syncthreads();

    // Q fragments (A operand), rows warp*16..+15, k=64 in 4 k16 steps.
    // Fold 0.125 * log2(e) into Q: softmax then runs in the exp2 domain.
    const uint32_t qB = smem_u32(smem);
    uint32_t qf[4][4];
    {
        const int row = wid * 16 + (l & 15);
        const int col = (l >> 4) << 3;
        const float qs = 0.125f * 1.44269504f;
        const __half2 sc = __floats2half2_rn(qs, qs);
#pragma unroll
        for (int ks = 0; ks < 4; ks++) {
            ldsm4(qf[ks], qB + (row * QP + ks * 16 + col) * 2);
#pragma unroll
            for (int e = 0; e < 4; e++) {
                __half2 v = __hmul2(*(__half2*)&qf[ks][e], sc);
                qf[ks][e] = *(uint32_t*)&v;
            }
        }
    }

    const int r0g = qb * 128 + wid * 16 + (l >> 2);   // global q row (part 0)
    const int r1g = r0g + 8;                          // part 1
    float m0r = -1e30f, m1r = -1e30f, l0r = 0.f, l1r = 0.f;
    float oacc[8][4];
#pragma unroll
    for (int f = 0; f < 8; f++)
#pragma unroll
        for (int e = 0; e < 4; e++) oacc[f][e] = 0.f;

    // lane offsets for K (non-trans B frags) and V (trans B frags)
    const int kRow = (l & 7) + ((l >> 4) << 3);
    const int kCol = ((l >> 3) & 1) << 3;
    const int vRow = (l & 7) + (((l >> 3) & 1) << 3);
    const int vCol = (l >> 4) << 3;

    const int jmax = 2 * qb + 1;
    for (int j = 0; j <= jmax; j++) {
        CP_WAIT_G1();          // tile j complete (tile j+1 may be in flight)
        __syncthreads();
        if (j + 2 <= jmax) attn_load_kv(smem, Kg, Vg, j + 2, tid);
        CP_COMMIT();           // unconditional: uniform group accounting

        const int st = j % A_NSTAGE;
        const uint32_t kB = smem_u32(smem + A_KOFF(st));
        const uint32_t vB = smem_u32(smem + A_VOFF(st));

        // ---- S = (Q*qs) @ K^T : 16x64 per warp (log2-domain scores) ----
        float sacc[8][4];
#pragma unroll
        for (int f = 0; f < 8; f++)
#pragma unroll
            for (int e = 0; e < 4; e++) sacc[f][e] = 0.f;

#pragma unroll
        for (int ks = 0; ks < 4; ks++) {
            uint32_t bf[4][4];
#pragma unroll
            for (int g = 0; g < 4; g++)
                ldsm4(bf[g], kB + ((g * 16 + kRow) * QP + ks * 16 + kCol) * 2);
#pragma unroll
            for (int f = 0; f < 8; f++) {
                const int g = f >> 1, o = (f & 1) * 2;
                mma16816(sacc[f], qf[ks], bf[g][o], bf[g][o + 1]);
            }
        }

        // ---- online softmax (thread-local rows r0g, r1g), exp2 domain ----
        const bool edge = (j >= 2 * qb);
        float mx0 = m0r, mx1 = m1r;
#pragma unroll
        for (int f = 0; f < 8; f++) {
            const int cb = j * 64 + f * 8 + ((l & 3) << 1);
            float v0 = sacc[f][0], v1 = sacc[f][1];
            float v2 = sacc[f][2], v3 = sacc[f][3];
            if (edge) {
                if (cb     > r0g) v0 = -1e30f;
                if (cb + 1 > r0g) v1 = -1e30f;
                if (cb     > r1g) v2 = -1e30f;
                if (cb + 1 > r1g) v3 = -1e30f;
            }
            sacc[f][0] = v0; sacc[f][1] = v1; sacc[f][2] = v2; sacc[f][3] = v3;
            mx0 = fmaxf(mx0, fmaxf(v0, v1));
            mx1 = fmaxf(mx1, fmaxf(v2, v3));
        }
        mx0 = fmaxf(mx0, __shfl_xor_sync(0xffffffffu, mx0, 1));
        mx0 = fmaxf(mx0, __shfl_xor_sync(0xffffffffu, mx0, 2));
        mx1 = fmaxf(mx1, __shfl_xor_sync(0xffffffffu, mx1, 1));
        mx1 = fmaxf(mx1, __shfl_xor_sync(0xffffffffu, mx1, 2));

        const float al0 = ex2f(m0r - mx0);
        const float al1 = ex2f(m1r - mx1);
        m0r = mx0; m1r = mx1;

        // packed fp16 exp2: P is produced directly in fp16; the row sum is
        // taken from the quantized P so l exactly matches the PV numerator.
        float s0 = 0.f, s1 = 0.f;
        uint32_t pl[8], ph[8];
#pragma unroll
        for (int f = 0; f < 8; f++) {
            pl[f] = ex2_h2(pack_h2(sacc[f][0] - mx0, sacc[f][1] - mx0));
            ph[f] = ex2_h2(pack_h2(sacc[f][2] - mx1, sacc[f][3] - mx1));
            const float2 q0 = __half22float2(*(__half2*)&pl[f]);
            const float2 q1 = __half22float2(*(__half2*)&ph[f]);
            s0 += q0.x + q0.y;
            s1 += q1.x + q1.y;
        }
        s0 += __shfl_xor_sync(0xffffffffu, s0, 1);
        s0 += __shfl_xor_sync(0xffffffffu, s0, 2);
        s1 += __shfl_xor_sync(0xffffffffu, s1, 1);
        s1 += __shfl_xor_sync(0xffffffffu, s1, 2);
        l0r = l0r * al0 + s0;
        l1r = l1r * al1 + s1;

        // ---- O = O*alpha + P @ V ----
#pragma unroll
        for (int f = 0; f < 8; f++) {
            oacc[f][0] *= al0; oacc[f][1] *= al0;
            oacc[f][2] *= al1; oacc[f][3] *= al1;
        }
#pragma unroll
        for (int ks = 0; ks < 4; ks++) {
            uint32_t a[4] = {pl[2 * ks], ph[2 * ks], pl[2 * ks + 1], ph[2 * ks + 1]};
            uint32_t bv[4][4];
#pragma unroll
            for (int g = 0; g < 4; g++)
                ldsm4t(bv[g], vB + ((ks * 16 + vRow) * QP + g * 16 + vCol) * 2);
#pragma unroll
            for (int f = 0; f < 8; f++) {
                const int g = f >> 1, o = (f & 1) * 2;
                mma16816(oacc[f], a, bv[g][o], bv[g][o + 1]);
            }
        }
    }

    // epilogue: ctx[row][h*64 + c] = O / l  (fp16)
    const float inv0 = 1.f / l0r, inv1 = 1.f / l1r;
#pragma unroll
    for (int f = 0; f < 8; f++) {
        const int cc = h * HD + f * 8 + ((l & 3) << 1);
        *(__half2*)&g_ctxh[(size_t)r0g * DIM + cc] =
            __floats2half2_rn(oacc[f][0] * inv0, oacc[f][1] * inv0);
        *(__half2*)&g_ctxh[(size_t)r1g * DIM + cc] =
            __floats2half2_rn(oacc[f][2] * inv1, oacc[f][3] * inv1);
    }
}

// ================================ launch ===================================
extern "C" void kernel_launch(void* const* d_in, const int* in_sizes, int n_in,
                              void* d_out, int out_size)
{
    (void)in_sizes; (void)n_in; (void)out_size;
    const float* x  = (const float*)d_in[0];
    const float* Wq = (const float*)d_in[1];
    const float* Wk = (const float*)d_in[2];
    const float* Wv = (const float*)d_in[3];
    const float* Wo = (const float*)d_in[4];
    const float* bo = (const float*)d_in[5];
    float* out = (float*)d_out;

    convert_kernel<<<8192, 256>>>(x, Wq, Wk, Wv, Wo);

    cudaFuncSetAttribute(gemm_proj_kernel,
                         cudaFuncAttributeMaxDynamicSharedMemorySize, GEMM_SMEM_TOT);
    gemm_proj_kernel<<<dim3(DIM / 128, SEQ / 128, 3), 256, GEMM_SMEM_TOT>>>();

    cudaFuncSetAttribute(attn_kernel,
                         cudaFuncAttributeMaxDynamicSharedMemorySize, ATTN_SMEM_TOT);
    attn_kernel<<<dim3(SEQ / 128, NH), 256, ATTN_SMEM_TOT>>>();

    cudaFuncSetAttribute(out_proj_kernel,
                         cudaFuncAttributeMaxDynamicSharedMemorySize, GEMM_SMEM_TOT);
    out_proj_kernel<<<dim3(DIM / 128, SEQ / 128), 256, GEMM_SMEM_TOT>>>(bo, out);
}